// round 16
// baseline (speedup 1.0000x reference)
#include <cuda_runtime.h>
#include <math.h>

#define B_    32
#define NCH   1024
#define NPTS  4096
#define MAXC  256        // max candidates per 1024-pt split
#define TAU   2.6f       // radius threshold (std normal; verified per channel)

__device__ int    g_imp[B_ * NCH];           // winner per (b, c)
__device__ float4 g_cand[B_ * 4 * MAXC];     // candidate points per (b, split)
__device__ int    g_ncand[B_ * 4];           // raw candidate counts

typedef unsigned long long ull;

__device__ __forceinline__ unsigned int ordf(float f) {
    unsigned int u = __float_as_uint(f);
    return (u & 0x80000000u) ? ~u : (u | 0x80000000u);
}

// ---------------------------------------------------------------------------
// Kernel 0: prep-lite. grid = 128 (b = blk>>2, split = blk&3), 1024 threads,
// 1 point/thread. Threshold compaction (ballot + popc, one shared counter),
// x passthrough folded in. No sorting, no histograms.
// ---------------------------------------------------------------------------
__global__ void __launch_bounds__(1024) prep_kernel(
    const float* __restrict__ x, float* __restrict__ out_x)
{
    __shared__ int scount;

    const int b    = blockIdx.x >> 2;
    const int s    = blockIdx.x & 3;
    const int t    = threadIdx.x;
    const int lane = t & 31;

    if (t == 0) scount = 0;

    const float* xb = x     + (size_t)b * 3 * NPTS + s * 1024;
    float*       ob = out_x + (size_t)b * 3 * NPTS + s * 1024;

    float a = xb[t], c = xb[NPTS + t], d = xb[2 * NPTS + t];
    ob[t] = a; ob[NPTS + t] = c; ob[2 * NPTS + t] = d;        // passthrough

    // r upper bound (_ru chain): excluded => true r < TAU guaranteed
    float r = __fsqrt_ru(__fmaf_ru(a, a, __fmaf_ru(c, c, __fmul_ru(d, d))));
    bool pred = (r >= TAU);

    __syncthreads();                       // scount = 0 visible
    unsigned bal  = __ballot_sync(0xffffffffu, pred);
    int      nw   = __popc(bal);
    int      rank = __popc(bal & ((1u << lane) - 1u));
    int base = 0;
    if (lane == 0 && nw) base = atomicAdd(&scount, nw);
    base = __shfl_sync(0xffffffffu, base, 0);
    if (pred) {
        int pos = base + rank;
        if (pos < MAXC)                     // overflow detected via raw count
            g_cand[((size_t)b * 4 + s) * MAXC + pos] =
                make_float4(a, c, d, __uint_as_float((unsigned)(s * 1024 + t)));
    }
    __syncthreads();
    if (t == 0) g_ncand[b * 4 + s] = scount;
}

// ---------------------------------------------------------------------------
// Kernel 1: candidate argmax + verification. WARP = channel; scans all
// candidates of the batch (no ordering needed), then checks that no excluded
// point could beat or tie (best >= |w|_ru * 1.00002 * TAU). On the (astronomi-
// cally rare) failure or candidate overflow: exact full scan of x.
// grid = 4096 (32 b x 128), 256 threads (8 channels/block).
// ---------------------------------------------------------------------------
__global__ void __launch_bounds__(256) argmax_kernel(
    const float* __restrict__ x, const float* __restrict__ W)
{
    __shared__ int scnt[4];

    const int b    = blockIdx.x >> 7;
    const int loc  = blockIdx.x & 127;
    const int lane = threadIdx.x & 31;
    const int wid  = threadIdx.x >> 5;
    const int c    = loc * 8 + wid;

    if (threadIdx.x < 4) scnt[threadIdx.x] = g_ncand[b * 4 + threadIdx.x];
    __syncthreads();

    const float w0 = W[c * 3 + 0];
    const float w1 = W[c * 3 + 1];
    const float w2 = W[c * 3 + 2];
    const float wn = __fsqrt_ru(__fmaf_ru(w0, w0,
                      __fmaf_ru(w1, w1, __fmul_ru(w2, w2))));
    const float ub = __fmul_ru(__fmul_ru(wn, 1.00002f), TAU);

    ull  kbest = 0;                        // (ordf(f)<<32) | (4095 - idx)
    bool over  = false;

    #pragma unroll
    for (int s = 0; s < 4; ++s) {
        int cnt = scnt[s];
        if (cnt > MAXC) { over = true; cnt = MAXC; }
        const float4* cp = g_cand + ((size_t)b * 4 + s) * MAXC;
        for (int j = lane; j < cnt; j += 32) {
            float4 p = cp[j];
            float f = __fmaf_rn(w2, p.z, __fmaf_rn(w1, p.y, __fmul_rn(w0, p.x)));
            ull key = ((ull)ordf(f) << 32) | (ull)(4095u - __float_as_uint(p.w));
            kbest = kbest > key ? kbest : key;
        }
    }

    #pragma unroll
    for (int o = 16; o; o >>= 1) {
        ull other = __shfl_xor_sync(0xffffffffu, kbest, o);
        kbest = kbest > other ? kbest : other;
    }

    // verification: excluded points have f < ub; need best >= ub (warp-uniform)
    if (over || (unsigned)(kbest >> 32) < ordf(ub)) {
        const float* x0 = x + (size_t)b * 3 * NPTS;
        const float* x1 = x0 + NPTS;
        const float* x2 = x0 + 2 * NPTS;
        kbest = 0;
        for (int i = lane; i < NPTS; i += 32) {
            float f = __fmaf_rn(w2, x2[i], __fmaf_rn(w1, x1[i], __fmul_rn(w0, x0[i])));
            ull key = ((ull)ordf(f) << 32) | (ull)(4095u - (unsigned)i);
            kbest = kbest > key ? kbest : key;
        }
        #pragma unroll
        for (int o = 16; o; o >>= 1) {
            ull other = __shfl_xor_sync(0xffffffffu, kbest, o);
            kbest = kbest > other ? kbest : other;
        }
    }

    if (lane == 0)
        g_imp[b * NCH + c] = 4095 - (int)(kbest & 0xFFFu);
}

// ---------------------------------------------------------------------------
// Kernel 2: counts, entropy, stable counting sort (R15-proven, verbatim).
// grid = 32, 1024 threads, ~70KB dynamic smem.
// ---------------------------------------------------------------------------
__global__ void __launch_bounds__(1024) sort_entropy_kernel(
    float* __restrict__ out_counts,
    float* __restrict__ out_imp2,
    float* __restrict__ out_ent)
{
    extern __shared__ __align__(16) char smem_raw[];
    int*            scnt   = (int*)smem_raw;                       // 16384
    int*            gstart = (int*)(smem_raw + 16384);             // 4100
    unsigned short* chh    = (unsigned short*)(smem_raw + 20488);  // 34852
    unsigned short* lrk    = (unsigned short*)(smem_raw + 55340);  // 8192
    unsigned short* sperm  = (unsigned short*)(smem_raw + 63536);  // 8192
    __shared__ float red[32];
    __shared__ int   ired[32];

    const int b    = blockIdx.x;
    const int t    = threadIdx.x;
    const int lane = t & 31;
    const int wid  = t >> 5;

    const int myimp = g_imp[b * NCH + t];   // prefetch before zeroing

    #pragma unroll
    for (int i = t; i < NPTS; i += 1024) scnt[i] = 0;
    for (int i = t; i < 8713; i += 1024) ((unsigned*)chh)[i] = 0;
    __syncthreads();

    atomicAdd(&scnt[myimp], 1);
    __syncthreads();

    const float inv_s = 1.0f / (1024.0f + 4096.0f * 1e-6f);
    float part2;
    {
        int4 cv = ((const int4*)scnt)[t];
        float4 cf = make_float4((float)cv.x, (float)cv.y, (float)cv.z, (float)cv.w);
        ((float4*)(out_counts + (size_t)b * NPTS))[t] = cf;
        float p0 = (cf.x + 1e-6f) * inv_s, p1 = (cf.y + 1e-6f) * inv_s;
        float p2 = (cf.z + 1e-6f) * inv_s, p3 = (cf.w + 1e-6f) * inv_s;
        part2 = p0 * __log2f(p0) + p1 * __log2f(p1)
              + p2 * __log2f(p2) + p3 * __log2f(p3);
    }

    // per-chunk stable local ranks (16 warps, chunk = 256 pts, 8 rounds)
    if (wid < 16) {
        #pragma unroll 1
        for (int r = 0; r < 8; ++r) {
            int n = (wid << 8) + (r << 5) + lane;
            int v = scnt[n];
            unsigned peers = __match_any_sync(0xffffffffu, v);
            int lr = __popc(peers & ((1u << lane) - 1u));
            int base = chh[v * 17 + wid];
            lrk[n] = (unsigned short)(base + lr);
            if (lane == (__ffs(peers) - 1))
                chh[v * 17 + wid] = (unsigned short)(base + __popc(peers));
            __syncwarp();
        }
    }
    __syncthreads();

    // entropy reduction
    #pragma unroll
    for (int o = 16; o; o >>= 1) part2 += __shfl_down_sync(0xffffffffu, part2, o);
    if (lane == 0) red[wid] = part2;
    __syncthreads();
    if (wid == 0) {
        float v = red[lane];
        #pragma unroll
        for (int o = 16; o; o >>= 1) v += __shfl_down_sync(0xffffffffu, v, o);
        if (lane == 0) out_ent[b] = -v * (1.0f / 12.0f);   // log2(4096)=12
    }

    // per-value prefix across 16 chunks (thread t <-> value t)
    int tot;
    {
        int run = 0;
        #pragma unroll
        for (int w = 0; w < 16; ++w) {
            int cc = chh[t * 17 + w];
            chh[t * 17 + w] = (unsigned short)run;
            run += cc;
        }
        tot = run;
        if (t == 0) {
            int r2 = 0;
            #pragma unroll
            for (int w = 0; w < 16; ++w) {
                int cc = chh[1024 * 17 + w];
                chh[1024 * 17 + w] = (unsigned short)r2;
                r2 += cc;
            }
            gstart[1024] = 4096 - r2;
        }
    }

    // parallel exclusive scan of value totals (0..1023)
    int incl = tot;
    #pragma unroll
    for (int o = 1; o < 32; o <<= 1) {
        int u = __shfl_up_sync(0xffffffffu, incl, o);
        if (lane >= o) incl += u;
    }
    if (lane == 31) ired[wid] = incl;
    __syncthreads();
    if (wid == 0) {
        int v = ired[lane];
        int sc = v;
        #pragma unroll
        for (int o = 1; o < 32; o <<= 1) {
            int u = __shfl_up_sync(0xffffffffu, sc, o);
            if (lane >= o) sc += u;
        }
        ired[lane] = sc - v;
    }
    __syncthreads();
    gstart[t] = incl - tot + ired[wid];
    __syncthreads();

    // ranks scatter into SHARED perm, then coalesced float4 write-out
    #pragma unroll
    for (int n = t; n < NPTS; n += 1024) {
        int v = scnt[n];
        int rank = gstart[v] + (int)chh[v * 17 + (n >> 8)] + (int)lrk[n];
        sperm[rank] = (unsigned short)n;
    }
    __syncthreads();
    {
        ushort4 s4 = ((const ushort4*)sperm)[t];
        ((float4*)(out_imp2 + (size_t)b * NPTS))[t] =
            make_float4((float)s4.x, (float)s4.y, (float)s4.z, (float)s4.w);
    }
}

// ---------------------------------------------------------------------------
extern "C" void kernel_launch(void* const* d_in, const int* in_sizes, int n_in,
                              void* d_out, int out_size)
{
    const float* x = (const float*)d_in[0];   // [32, 3, 4096]
    const float* W = (const float*)d_in[1];   // [1024, 3]
    float* out = (float*)d_out;

    float* out_x      = out;
    float* out_counts = out + B_ * 3 * NPTS;
    float* out_imp2   = out_counts + B_ * NPTS;
    float* out_ent    = out_imp2 + B_ * NPTS;

    const int SORT_SMEM = 71744;
    cudaFuncSetAttribute(sort_entropy_kernel,
                         cudaFuncAttributeMaxDynamicSharedMemorySize, SORT_SMEM);

    prep_kernel<<<B_ * 4, 1024>>>(x, out_x);
    argmax_kernel<<<B_ * 128, 256>>>(x, W);
    sort_entropy_kernel<<<B_, 1024, SORT_SMEM>>>(out_counts, out_imp2, out_ent);
}

// round 17
// speedup vs baseline: 1.0066x; 1.0066x over previous
#include <cuda_runtime.h>
#include <math.h>

#define B_    32
#define NCH   1024
#define NPTS  4096
#define MAXC  256        // max candidates per 1024-pt split
#define TAU   2.6f       // radius threshold (std normal; verified per channel)

__device__ int    g_imp[B_ * NCH];           // winner per (b, c)
__device__ float4 g_cand[B_ * 4 * MAXC];     // candidate points per (b, split)
__device__ int    g_ncand[B_ * 4];           // raw candidate counts

typedef unsigned long long ull;

__device__ __forceinline__ unsigned int ordf(float f) {
    unsigned int u = __float_as_uint(f);
    return (u & 0x80000000u) ? ~u : (u | 0x80000000u);
}

// ---------------------------------------------------------------------------
// Kernel 0: prep-lite (R16, measured 4.7us). grid = 128 (b = blk>>2, s = blk&3),
// 1024 threads, 1 point/thread. Threshold compaction + x passthrough.
// ---------------------------------------------------------------------------
__global__ void __launch_bounds__(1024) prep_kernel(
    const float* __restrict__ x, float* __restrict__ out_x)
{
    __shared__ int scount;

    const int b    = blockIdx.x >> 2;
    const int s    = blockIdx.x & 3;
    const int t    = threadIdx.x;
    const int lane = t & 31;

    if (t == 0) scount = 0;

    const float* xb = x     + (size_t)b * 3 * NPTS + s * 1024;
    float*       ob = out_x + (size_t)b * 3 * NPTS + s * 1024;

    float a = xb[t], c = xb[NPTS + t], d = xb[2 * NPTS + t];
    ob[t] = a; ob[NPTS + t] = c; ob[2 * NPTS + t] = d;        // passthrough

    // r upper bound (_ru chain): excluded => true r < TAU guaranteed
    float r = __fsqrt_ru(__fmaf_ru(a, a, __fmaf_ru(c, c, __fmul_ru(d, d))));
    bool pred = (r >= TAU);

    __syncthreads();                       // scount = 0 visible
    unsigned bal  = __ballot_sync(0xffffffffu, pred);
    int      nw   = __popc(bal);
    int      rank = __popc(bal & ((1u << lane) - 1u));
    int base = 0;
    if (lane == 0 && nw) base = atomicAdd(&scount, nw);
    base = __shfl_sync(0xffffffffu, base, 0);
    if (pred) {
        int pos = base + rank;
        if (pos < MAXC)                     // overflow detected via raw count
            g_cand[((size_t)b * 4 + s) * MAXC + pos] =
                make_float4(a, c, d, __uint_as_float((unsigned)(s * 1024 + t)));
    }
    __syncthreads();
    if (t == 0) g_ncand[b * 4 + s] = scount;
}

// ---------------------------------------------------------------------------
// Kernel 1: candidate argmax + verification, MLP-4 batched loads.
// WARP = channel. Guard-miss lanes use a zero point: its key can only win
// when best < ub, which already forces the exact full-scan fallback.
// grid = 4096 (32 b x 128), 256 threads (8 channels/block).
// ---------------------------------------------------------------------------
__global__ void __launch_bounds__(256) argmax_kernel(
    const float* __restrict__ x, const float* __restrict__ W)
{
    __shared__ int scnt[4];

    const int b    = blockIdx.x >> 7;
    const int loc  = blockIdx.x & 127;
    const int lane = threadIdx.x & 31;
    const int wid  = threadIdx.x >> 5;
    const int c    = loc * 8 + wid;

    if (threadIdx.x < 4) scnt[threadIdx.x] = g_ncand[b * 4 + threadIdx.x];
    __syncthreads();

    const float w0 = W[c * 3 + 0];
    const float w1 = W[c * 3 + 1];
    const float w2 = W[c * 3 + 2];
    const float wn = __fsqrt_ru(__fmaf_ru(w0, w0,
                      __fmaf_ru(w1, w1, __fmul_ru(w2, w2))));
    const float ub = __fmul_ru(__fmul_ru(wn, 1.00002f), TAU);

    ull  kbest = 0;                        // (ordf(f)<<32) | (4095 - idx)
    bool over  = false;

    const float4 z4 = make_float4(0.f, 0.f, 0.f, 0.f);

    #pragma unroll
    for (int s = 0; s < 4; ++s) {
        int cnt = scnt[s];
        if (cnt > MAXC) { over = true; cnt = MAXC; }
        const float4* cp = g_cand + ((size_t)b * 4 + s) * MAXC;
        #pragma unroll 1
        for (int j = lane; j < cnt; j += 128) {
            // 4 independent loads issue before any consume (MLP = 4)
            float4 p0 = cp[j];
            float4 p1 = (j +  32 < cnt) ? cp[j +  32] : z4;
            float4 p2 = (j +  64 < cnt) ? cp[j +  64] : z4;
            float4 p3 = (j +  96 < cnt) ? cp[j +  96] : z4;

            float f0 = __fmaf_rn(w2, p0.z, __fmaf_rn(w1, p0.y, __fmul_rn(w0, p0.x)));
            float f1 = __fmaf_rn(w2, p1.z, __fmaf_rn(w1, p1.y, __fmul_rn(w0, p1.x)));
            float f2 = __fmaf_rn(w2, p2.z, __fmaf_rn(w1, p2.y, __fmul_rn(w0, p2.x)));
            float f3 = __fmaf_rn(w2, p3.z, __fmaf_rn(w1, p3.y, __fmul_rn(w0, p3.x)));

            ull k0 = ((ull)ordf(f0) << 32) | (ull)(4095u - __float_as_uint(p0.w));
            ull k1 = ((ull)ordf(f1) << 32) | (ull)(4095u - __float_as_uint(p1.w));
            ull k2 = ((ull)ordf(f2) << 32) | (ull)(4095u - __float_as_uint(p2.w));
            ull k3 = ((ull)ordf(f3) << 32) | (ull)(4095u - __float_as_uint(p3.w));

            ull ka = k0 > k1 ? k0 : k1;
            ull kb2 = k2 > k3 ? k2 : k3;
            ull kc = ka > kb2 ? ka : kb2;
            kbest = kbest > kc ? kbest : kc;
        }
    }

    #pragma unroll
    for (int o = 16; o; o >>= 1) {
        ull other = __shfl_xor_sync(0xffffffffu, kbest, o);
        kbest = kbest > other ? kbest : other;
    }

    // verification: excluded points have f < ub; need best >= ub (warp-uniform)
    if (over || (unsigned)(kbest >> 32) < ordf(ub)) {
        const float* x0 = x + (size_t)b * 3 * NPTS;
        const float* x1 = x0 + NPTS;
        const float* x2 = x0 + 2 * NPTS;
        kbest = 0;
        for (int i = lane; i < NPTS; i += 32) {
            float f = __fmaf_rn(w2, x2[i], __fmaf_rn(w1, x1[i], __fmul_rn(w0, x0[i])));
            ull key = ((ull)ordf(f) << 32) | (ull)(4095u - (unsigned)i);
            kbest = kbest > key ? kbest : key;
        }
        #pragma unroll
        for (int o = 16; o; o >>= 1) {
            ull other = __shfl_xor_sync(0xffffffffu, kbest, o);
            kbest = kbest > other ? kbest : other;
        }
    }

    if (lane == 0)
        g_imp[b * NCH + c] = 4095 - (int)(kbest & 0xFFFu);
}

// ---------------------------------------------------------------------------
// Kernel 2: counts, entropy, stable counting sort (proven, verbatim).
// grid = 32, 1024 threads, ~70KB dynamic smem.
// ---------------------------------------------------------------------------
__global__ void __launch_bounds__(1024) sort_entropy_kernel(
    float* __restrict__ out_counts,
    float* __restrict__ out_imp2,
    float* __restrict__ out_ent)
{
    extern __shared__ __align__(16) char smem_raw[];
    int*            scnt   = (int*)smem_raw;                       // 16384
    int*            gstart = (int*)(smem_raw + 16384);             // 4100
    unsigned short* chh    = (unsigned short*)(smem_raw + 20488);  // 34852
    unsigned short* lrk    = (unsigned short*)(smem_raw + 55340);  // 8192
    unsigned short* sperm  = (unsigned short*)(smem_raw + 63536);  // 8192
    __shared__ float red[32];
    __shared__ int   ired[32];

    const int b    = blockIdx.x;
    const int t    = threadIdx.x;
    const int lane = t & 31;
    const int wid  = t >> 5;

    const int myimp = g_imp[b * NCH + t];   // prefetch before zeroing

    #pragma unroll
    for (int i = t; i < NPTS; i += 1024) scnt[i] = 0;
    for (int i = t; i < 8713; i += 1024) ((unsigned*)chh)[i] = 0;
    __syncthreads();

    atomicAdd(&scnt[myimp], 1);
    __syncthreads();

    const float inv_s = 1.0f / (1024.0f + 4096.0f * 1e-6f);
    float part2;
    {
        int4 cv = ((const int4*)scnt)[t];
        float4 cf = make_float4((float)cv.x, (float)cv.y, (float)cv.z, (float)cv.w);
        ((float4*)(out_counts + (size_t)b * NPTS))[t] = cf;
        float p0 = (cf.x + 1e-6f) * inv_s, p1 = (cf.y + 1e-6f) * inv_s;
        float p2 = (cf.z + 1e-6f) * inv_s, p3 = (cf.w + 1e-6f) * inv_s;
        part2 = p0 * __log2f(p0) + p1 * __log2f(p1)
              + p2 * __log2f(p2) + p3 * __log2f(p3);
    }

    // per-chunk stable local ranks (16 warps, chunk = 256 pts, 8 rounds)
    if (wid < 16) {
        #pragma unroll 1
        for (int r = 0; r < 8; ++r) {
            int n = (wid << 8) + (r << 5) + lane;
            int v = scnt[n];
            unsigned peers = __match_any_sync(0xffffffffu, v);
            int lr = __popc(peers & ((1u << lane) - 1u));
            int base = chh[v * 17 + wid];
            lrk[n] = (unsigned short)(base + lr);
            if (lane == (__ffs(peers) - 1))
                chh[v * 17 + wid] = (unsigned short)(base + __popc(peers));
            __syncwarp();
        }
    }
    __syncthreads();

    // entropy reduction
    #pragma unroll
    for (int o = 16; o; o >>= 1) part2 += __shfl_down_sync(0xffffffffu, part2, o);
    if (lane == 0) red[wid] = part2;
    __syncthreads();
    if (wid == 0) {
        float v = red[lane];
        #pragma unroll
        for (int o = 16; o; o >>= 1) v += __shfl_down_sync(0xffffffffu, v, o);
        if (lane == 0) out_ent[b] = -v * (1.0f / 12.0f);   // log2(4096)=12
    }

    // per-value prefix across 16 chunks (thread t <-> value t)
    int tot;
    {
        int run = 0;
        #pragma unroll
        for (int w = 0; w < 16; ++w) {
            int cc = chh[t * 17 + w];
            chh[t * 17 + w] = (unsigned short)run;
            run += cc;
        }
        tot = run;
        if (t == 0) {
            int r2 = 0;
            #pragma unroll
            for (int w = 0; w < 16; ++w) {
                int cc = chh[1024 * 17 + w];
                chh[1024 * 17 + w] = (unsigned short)r2;
                r2 += cc;
            }
            gstart[1024] = 4096 - r2;
        }
    }

    // parallel exclusive scan of value totals (0..1023)
    int incl = tot;
    #pragma unroll
    for (int o = 1; o < 32; o <<= 1) {
        int u = __shfl_up_sync(0xffffffffu, incl, o);
        if (lane >= o) incl += u;
    }
    if (lane == 31) ired[wid] = incl;
    __syncthreads();
    if (wid == 0) {
        int v = ired[lane];
        int sc = v;
        #pragma unroll
        for (int o = 1; o < 32; o <<= 1) {
            int u = __shfl_up_sync(0xffffffffu, sc, o);
            if (lane >= o) sc += u;
        }
        ired[lane] = sc - v;
    }
    __syncthreads();
    gstart[t] = incl - tot + ired[wid];
    __syncthreads();

    // ranks scatter into SHARED perm, then coalesced float4 write-out
    #pragma unroll
    for (int n = t; n < NPTS; n += 1024) {
        int v = scnt[n];
        int rank = gstart[v] + (int)chh[v * 17 + (n >> 8)] + (int)lrk[n];
        sperm[rank] = (unsigned short)n;
    }
    __syncthreads();
    {
        ushort4 s4 = ((const ushort4*)sperm)[t];
        ((float4*)(out_imp2 + (size_t)b * NPTS))[t] =
            make_float4((float)s4.x, (float)s4.y, (float)s4.z, (float)s4.w);
    }
}

// ---------------------------------------------------------------------------
extern "C" void kernel_launch(void* const* d_in, const int* in_sizes, int n_in,
                              void* d_out, int out_size)
{
    const float* x = (const float*)d_in[0];   // [32, 3, 4096]
    const float* W = (const float*)d_in[1];   // [1024, 3]
    float* out = (float*)d_out;

    float* out_x      = out;
    float* out_counts = out + B_ * 3 * NPTS;
    float* out_imp2   = out_counts + B_ * NPTS;
    float* out_ent    = out_imp2 + B_ * NPTS;

    const int SORT_SMEM = 71744;
    cudaFuncSetAttribute(sort_entropy_kernel,
                         cudaFuncAttributeMaxDynamicSharedMemorySize, SORT_SMEM);

    prep_kernel<<<B_ * 4, 1024>>>(x, out_x);
    argmax_kernel<<<B_ * 128, 256>>>(x, W);
    sort_entropy_kernel<<<B_, 1024, SORT_SMEM>>>(out_counts, out_imp2, out_ent);
}